// round 1
// baseline (speedup 1.0000x reference)
#include <cuda_runtime.h>
#include <math.h>
#include <stdint.h>

// ---------------- problem-size bounds (from reference) ----------------
#define NMAX 50048      // nodes (actual 50000)
#define EMAX 600064     // edges (actual 600000)
#define GMAX 2048       // graphs

// ---------------- scratch (device globals; no allocation) ----------------
__device__ int   g_deg[NMAX];
__device__ int   g_off[NMAX];
__device__ int   g_pos[NMAX];
__device__ int   g_srt_src[EMAX];

__device__ float g_h [NMAX * 128];   // current node features (64/128/64/32 wide)
__device__ float g_M [NMAX * 128];   // aggregated relu means
__device__ float g_AB[NMAX * 256];   // per-node [A | B] for the edge phase

__device__ float g_Wc1[64 * 256],  g_bc1[256];
__device__ float g_Wc2[128 * 128], g_bc2[128];
__device__ float g_Wc3[64 * 64],   g_bc3[64];

__device__ float g_pool[GMAX * 32];
__device__ float g_gcnt[GMAX];

// ---------------- small utility kernels ----------------
__global__ void zero_kernel(int n, int g) {
    int i = blockIdx.x * blockDim.x + threadIdx.x;
    if (i < n)      g_deg[i]  = 0;
    if (i < g * 32) g_pool[i] = 0.f;
    if (i < g)      g_gcnt[i] = 0.f;
}

__global__ void hist_kernel(const int* __restrict__ dst, int e) {
    int i = blockIdx.x * blockDim.x + threadIdx.x;
    if (i < e) atomicAdd(&g_deg[dst[i]], 1);
}

// single-block exclusive scan of g_deg -> g_off (and g_pos copy)
__global__ void scan_kernel(int n) {
    __shared__ int sh[1024];
    int tid = threadIdx.x;
    int carry = 0;
    for (int base = 0; base < n; base += 1024) {
        int i = base + tid;
        int v = (i < n) ? g_deg[i] : 0;
        sh[tid] = v;
        __syncthreads();
        #pragma unroll
        for (int step = 1; step < 1024; step <<= 1) {
            int t = (tid >= step) ? sh[tid - step] : 0;
            __syncthreads();
            sh[tid] += t;
            __syncthreads();
        }
        int excl = sh[tid] - v;
        if (i < n) { g_off[i] = carry + excl; g_pos[i] = carry + excl; }
        int tot = sh[1023];
        __syncthreads();
        carry += tot;
        __syncthreads();
    }
}

__global__ void scatter_kernel(const int* __restrict__ src,
                               const int* __restrict__ dst, int e) {
    int i = blockIdx.x * blockDim.x + threadIdx.x;
    if (i < e) {
        int p = atomicAdd(&g_pos[dst[i]], 1);
        g_srt_src[p] = src[i];
    }
}

// Build combined weight Wc[D][2H]: cols [0,H) = Wtop - Wbot, [H,2H) = Wbot,
// combined bias bc[2H]: [0,H) = b, [H,2H) = 0.
__global__ void prep_kernel(const float* __restrict__ W, const float* __restrict__ b,
                            float* __restrict__ Wc, float* __restrict__ bc,
                            int D, int H) {
    int total = D * 2 * H;
    for (int i = blockIdx.x * blockDim.x + threadIdx.x; i < total;
         i += gridDim.x * blockDim.x) {
        int k = i / (2 * H), c = i % (2 * H);
        if (c < H) Wc[i] = W[k * H + c] - W[(k + D) * H + c];
        else       Wc[i] = W[(k + D) * H + (c - H)];
        if (i < 2 * H) bc[i] = (i < H) ? b[i] : 0.f;
    }
}

// ---------------- SGEMM: Y[N,H] = X[N,K] @ W[K,H] (+ epilogue) ----------------
// EPI=0: Y = acc + bias[c]
// EPI=1: Y = relu((acc + bias[c]*[deg>0]) * g[c]/sqrt(1+eps) + beta[c])
template <int K, int H, int HB, int EPI>
__global__ void gemm_kernel(const float* __restrict__ X, const float* __restrict__ W,
                            float* __restrict__ Y, const float* __restrict__ bias,
                            const float* __restrict__ gam, const float* __restrict__ bet,
                            int nrows) {
    constexpr int TX = HB / 4;        // threads along cols
    constexpr int TY = 256 / TX;      // threads along rows
    constexpr int TM = TY * 4;        // rows per block

    __shared__ float sA[16][TM];
    __shared__ float sB[16][HB];

    const int row0 = blockIdx.x * TM;
    const int c0   = blockIdx.y * HB;
    const int tid  = threadIdx.x;
    const int tx   = tid % TX;
    const int ty   = tid / TX;

    float acc[4][4];
    #pragma unroll
    for (int i = 0; i < 4; i++)
        #pragma unroll
        for (int j = 0; j < 4; j++) acc[i][j] = 0.f;

    for (int kt = 0; kt < K; kt += 16) {
        // load A tile (transposed into smem)
        #pragma unroll
        for (int rr = 0; rr < TM; rr += 64) {
            int r  = rr + (tid >> 2);
            int k4 = (tid & 3) * 4;
            float4 v = make_float4(0.f, 0.f, 0.f, 0.f);
            int grow = row0 + r;
            if (grow < nrows)
                v = *(const float4*)&X[(size_t)grow * K + kt + k4];
            sA[k4 + 0][r] = v.x; sA[k4 + 1][r] = v.y;
            sA[k4 + 2][r] = v.z; sA[k4 + 3][r] = v.w;
        }
        // load W tile
        constexpr int HB4 = HB / 4;
        for (int t = tid; t < 16 * HB4; t += 256) {
            int k  = t / HB4;
            int c4 = (t % HB4) * 4;
            *(float4*)&sB[k][c4] =
                *(const float4*)&W[(size_t)(kt + k) * H + c0 + c4];
        }
        __syncthreads();

        #pragma unroll
        for (int k = 0; k < 16; k++) {
            float4 a = *(const float4*)&sA[k][ty * 4];
            float4 b = *(const float4*)&sB[k][tx * 4];
            float av[4] = {a.x, a.y, a.z, a.w};
            float bv[4] = {b.x, b.y, b.z, b.w};
            #pragma unroll
            for (int i = 0; i < 4; i++)
                #pragma unroll
                for (int j = 0; j < 4; j++)
                    acc[i][j] = fmaf(av[i], bv[j], acc[i][j]);
        }
        __syncthreads();
    }

    const float rs = rsqrtf(1.f + 1e-5f);
    #pragma unroll
    for (int i = 0; i < 4; i++) {
        int grow = row0 + ty * 4 + i;
        if (grow >= nrows) continue;
        float ind = 1.f;
        if (EPI == 1) ind = (g_deg[grow] > 0) ? 1.f : 0.f;
        #pragma unroll
        for (int j = 0; j < 4; j++) {
            int c = c0 + tx * 4 + j;
            float v;
            if (EPI == 0) {
                v = acc[i][j] + bias[c];
            } else {
                v = acc[i][j] + bias[c] * ind;
                v = fmaxf(fmaf(v, gam[c] * rs, bet[c]), 0.f);
            }
            Y[(size_t)grow * H + c] = v;
        }
    }
}

// ---------------- edge aggregation: M[v] = mean_{e: dst=v} relu(A[v]+B[src_e]) --
template <int H>
__global__ void edge_agg_kernel(int n) {
    constexpr int VPL = H / 32;
    int w    = (blockIdx.x * blockDim.x + threadIdx.x) >> 5;
    int lane = threadIdx.x & 31;
    if (w >= n) return;

    const float* Arow = g_AB + (size_t)w * (2 * H);
    float a[VPL], acc[VPL];
    #pragma unroll
    for (int j = 0; j < VPL; j++) { a[j] = Arow[lane + 32 * j]; acc[j] = 0.f; }

    int st = g_off[w];
    int d  = g_deg[w];
    for (int e = st; e < st + d; e++) {
        int s = g_srt_src[e];
        const float* Brow = g_AB + (size_t)s * (2 * H) + H;
        #pragma unroll
        for (int j = 0; j < VPL; j++)
            acc[j] += fmaxf(a[j] + Brow[lane + 32 * j], 0.f);
    }
    float inv = 1.f / (float)max(d, 1);
    #pragma unroll
    for (int j = 0; j < VPL; j++)
        g_M[(size_t)w * H + lane + 32 * j] = acc[j] * inv;
}

// ---------------- pooling + classifier ----------------
__global__ void pool_kernel(const int* __restrict__ batch, int n) {
    int i = blockIdx.x * blockDim.x + threadIdx.x;
    if (i >= n * 32) return;
    int v = i >> 5, c = i & 31;
    int b = batch[v];
    atomicAdd(&g_pool[b * 32 + c], g_h[(size_t)v * 32 + c]);
    if (c == 0) atomicAdd(&g_gcnt[b], 1.f);
}

__global__ void final_kernel(const float* __restrict__ Wfc,
                             const float* __restrict__ bfc,
                             float* __restrict__ out, int g) {
    int t = blockIdx.x * blockDim.x + threadIdx.x;
    if (t >= g * 5) return;
    int gi = t / 5, o = t % 5;
    float inv = 1.f / fmaxf(g_gcnt[gi], 1.f);
    float z = bfc[o];
    #pragma unroll
    for (int k = 0; k < 32; k++)
        z = fmaf(g_pool[gi * 32 + k] * inv, Wfc[k * 5 + o], z);
    out[t] = 1.f / (1.f + expf(-z));
}

// ---------------- launch ----------------
static inline int cdiv(int a, int b) { return (a + b - 1) / b; }

extern "C" void kernel_launch(void* const* d_in, const int* in_sizes, int n_in,
                              void* d_out, int out_size) {
    const float* x     = (const float*)d_in[0];
    const float* Wn    = (const float*)d_in[4];
    const float* bnode = (const float*)d_in[5];
    const float* W1a   = (const float*)d_in[6];
    const float* b1a   = (const float*)d_in[7];
    const float* W1b   = (const float*)d_in[8];
    const float* b1b   = (const float*)d_in[9];
    const float* W2a   = (const float*)d_in[10];
    const float* b2a   = (const float*)d_in[11];
    const float* W2b   = (const float*)d_in[12];
    const float* b2b   = (const float*)d_in[13];
    const float* W3a   = (const float*)d_in[14];
    const float* b3a   = (const float*)d_in[15];
    const float* W3b   = (const float*)d_in[16];
    const float* b3b   = (const float*)d_in[17];
    const float* gm1   = (const float*)d_in[18];
    const float* bt1   = (const float*)d_in[19];
    const float* gm2   = (const float*)d_in[20];
    const float* bt2   = (const float*)d_in[21];
    const float* gm3   = (const float*)d_in[22];
    const float* bt3   = (const float*)d_in[23];
    const float* Wfc   = (const float*)d_in[24];
    const float* bfc   = (const float*)d_in[25];
    const int*   ei    = (const int*)d_in[26];
    const int*   batch = (const int*)d_in[27];

    const int n = in_sizes[0] / 32;      // 50000
    const int e = in_sizes[26] / 2;      // 600000
    const int g = out_size / 5;          // 2048

    const int* src = ei;
    const int* dst = ei + e;

    float *h, *M, *AB, *Wc1, *bc1, *Wc2, *bc2, *Wc3, *bc3;
    cudaGetSymbolAddress((void**)&h,   g_h);
    cudaGetSymbolAddress((void**)&M,   g_M);
    cudaGetSymbolAddress((void**)&AB,  g_AB);
    cudaGetSymbolAddress((void**)&Wc1, g_Wc1);
    cudaGetSymbolAddress((void**)&bc1, g_bc1);
    cudaGetSymbolAddress((void**)&Wc2, g_Wc2);
    cudaGetSymbolAddress((void**)&bc2, g_bc2);
    cudaGetSymbolAddress((void**)&Wc3, g_Wc3);
    cudaGetSymbolAddress((void**)&bc3, g_bc3);

    int zmax = max(n, g * 32);
    zero_kernel<<<cdiv(zmax, 256), 256>>>(n, g);
    hist_kernel<<<cdiv(e, 256), 256>>>(dst, e);
    scan_kernel<<<1, 1024>>>(n);
    scatter_kernel<<<cdiv(e, 256), 256>>>(src, dst, e);

    prep_kernel<<<64, 256>>>(W1a, b1a, Wc1, bc1, 64, 128);
    prep_kernel<<<64, 256>>>(W2a, b2a, Wc2, bc2, 128, 64);
    prep_kernel<<<64, 256>>>(W3a, b3a, Wc3, bc3, 64, 32);

    // h0 = x @ Wn + bnode           [N,64]
    gemm_kernel<32, 64, 64, 0><<<dim3(cdiv(n, 64), 1), 256>>>(
        x, Wn, h, bnode, nullptr, nullptr, n);

    // ---- layer 1 ----
    gemm_kernel<64, 256, 64, 0><<<dim3(cdiv(n, 64), 4), 256>>>(
        h, Wc1, AB, bc1, nullptr, nullptr, n);
    edge_agg_kernel<128><<<cdiv(n, 8), 256>>>(n);
    gemm_kernel<128, 128, 64, 1><<<dim3(cdiv(n, 64), 2), 256>>>(
        M, W1b, h, b1b, gm1, bt1, n);

    // ---- layer 2 ----
    gemm_kernel<128, 128, 64, 0><<<dim3(cdiv(n, 64), 2), 256>>>(
        h, Wc2, AB, bc2, nullptr, nullptr, n);
    edge_agg_kernel<64><<<cdiv(n, 8), 256>>>(n);
    gemm_kernel<64, 64, 64, 1><<<dim3(cdiv(n, 64), 1), 256>>>(
        M, W2b, h, b2b, gm2, bt2, n);

    // ---- layer 3 ----
    gemm_kernel<64, 64, 64, 0><<<dim3(cdiv(n, 64), 1), 256>>>(
        h, Wc3, AB, bc3, nullptr, nullptr, n);
    edge_agg_kernel<32><<<cdiv(n, 8), 256>>>(n);
    gemm_kernel<32, 32, 32, 1><<<dim3(cdiv(n, 128), 1), 256>>>(
        M, W3b, h, b3b, gm3, bt3, n);

    // ---- pool + classifier ----
    pool_kernel<<<cdiv(n * 32, 256), 256>>>(batch, n);
    final_kernel<<<cdiv(g * 5, 256), 256>>>(Wfc, bfc, (float*)d_out, g);
}

// round 3
// speedup vs baseline: 1.9327x; 1.9327x over previous
#include <cuda_runtime.h>
#include <math.h>
#include <stdint.h>

// ---------------- problem-size bounds ----------------
#define NMAX 50048
#define EMAX 600064
#define GMAX 2048

// ---------------- scratch (device globals) ----------------
__device__ int   g_deg[NMAX];
__device__ int   g_off[NMAX];
__device__ int   g_pos[NMAX];
__device__ int   g_total;
__device__ int   g_srt_src[EMAX];

__device__ float g_h [NMAX * 128];
__device__ float g_M [NMAX * 128];
__device__ float g_AB[NMAX * 256];

__device__ float g_Wc1[64 * 256],  g_bc1[256];
__device__ float g_Wc2[128 * 128], g_bc2[128];
__device__ float g_Wc3[64 * 64],   g_bc3[64];

__device__ float g_pool[GMAX * 32];
__device__ float g_gcnt[GMAX];

// ---------------- small utility kernels ----------------
__global__ void zero_kernel(int n, int g) {
    int i = blockIdx.x * blockDim.x + threadIdx.x;
    if (i == 0)     g_total   = 0;
    if (i < n)      g_deg[i]  = 0;
    if (i < g * 32) g_pool[i] = 0.f;
    if (i < g)      g_gcnt[i] = 0.f;
}

__global__ void hist_kernel(const int* __restrict__ dst, int e) {
    int i = blockIdx.x * blockDim.x + threadIdx.x;
    if (i < e) atomicAdd(&g_deg[dst[i]], 1);
}

// Warp-aggregated range allocation: g_off[v] gets a disjoint range of size deg[v].
// (Order across nodes is irrelevant for mean aggregation.)
__global__ void alloc_kernel(int n) {
    int i = blockIdx.x * blockDim.x + threadIdx.x;
    int lane = threadIdx.x & 31;
    int d = (i < n) ? g_deg[i] : 0;
    int pre = d;
    #pragma unroll
    for (int s = 1; s < 32; s <<= 1) {
        int t = __shfl_up_sync(0xffffffffu, pre, s);
        if (lane >= s) pre += t;
    }
    int wsum = __shfl_sync(0xffffffffu, pre, 31);
    int base = 0;
    if (lane == 31) base = atomicAdd(&g_total, wsum);
    base = __shfl_sync(0xffffffffu, base, 31);
    int off = base + pre - d;
    if (i < n) { g_off[i] = off; g_pos[i] = off; }
}

__global__ void scatter_kernel(const int* __restrict__ src,
                               const int* __restrict__ dst, int e) {
    int i = blockIdx.x * blockDim.x + threadIdx.x;
    if (i < e) {
        int p = atomicAdd(&g_pos[dst[i]], 1);
        g_srt_src[p] = src[i];
    }
}

// Wc[D][2H]: cols [0,H) = Wtop - Wbot, [H,2H) = Wbot; bc: [b | 0].
__global__ void prep_kernel(const float* __restrict__ W, const float* __restrict__ b,
                            float* __restrict__ Wc, float* __restrict__ bc,
                            int D, int H) {
    int total = D * 2 * H;
    for (int i = blockIdx.x * blockDim.x + threadIdx.x; i < total;
         i += gridDim.x * blockDim.x) {
        int k = i / (2 * H), c = i % (2 * H);
        if (c < H) Wc[i] = W[k * H + c] - W[(k + D) * H + c];
        else       Wc[i] = W[(k + D) * H + (c - H)];
        if (i < 2 * H) bc[i] = (i < H) ? b[i] : 0.f;
    }
}

// ---------------- tf32 tensor-core GEMM ----------------
__device__ __forceinline__ uint32_t f2tf(float f) {
    uint32_t u;
    asm("cvt.rna.tf32.f32 %0, %1;" : "=r"(u) : "f"(f));
    return u;
}

__device__ __forceinline__ void mma_tf32(float* c, const uint32_t* a, const uint32_t* b) {
    asm volatile(
        "mma.sync.aligned.m16n8k8.row.col.f32.tf32.tf32.f32 "
        "{%0,%1,%2,%3}, {%4,%5,%6,%7}, {%8,%9}, {%0,%1,%2,%3};"
        : "+f"(c[0]), "+f"(c[1]), "+f"(c[2]), "+f"(c[3])
        : "r"(a[0]), "r"(a[1]), "r"(a[2]), "r"(a[3]), "r"(b[0]), "r"(b[1]));
}

// Y[N,H] = X[N,K] @ W[K,H]  (+ epilogue)
// EPI=0: Y = acc + bias[c]
// EPI=1: Y = relu((acc + bias[c]*[deg>0]) * g[c]/sqrt(1+eps) + beta[c])
template <int K, int H, int EPI>
__global__ __launch_bounds__(256)
void mma_gemm(const float* __restrict__ X, const float* __restrict__ W,
              float* __restrict__ Y, const float* __restrict__ bias,
              const float* __restrict__ gam, const float* __restrict__ bet,
              int nrows) {
    constexpr int BN  = (H < 64) ? H : 64;
    constexpr int WN  = BN / 32;          // warps along n
    constexpr int WM  = 8 / WN;           // warps along m
    constexpr int BM  = WM * 32;          // 128 or 256
    constexpr int KC  = 32;
    constexpr int KCP = KC + 4;           // pad -> conflict-free frag loads
    constexpr int BNP = BN + 8;

    __shared__ uint32_t sA[BM * KCP];
    __shared__ uint32_t sB[KC * BNP];

    const int tid  = threadIdx.x;
    const int lane = tid & 31;
    const int wid  = tid >> 5;
    const int wm   = wid % WM;
    const int wn   = wid / WM;
    const int row0 = blockIdx.x * BM;
    const int c0   = blockIdx.y * BN;

    float acc[2][4][4];
    #pragma unroll
    for (int mi = 0; mi < 2; mi++)
        #pragma unroll
        for (int nj = 0; nj < 4; nj++)
            #pragma unroll
            for (int q = 0; q < 4; q++) acc[mi][nj][q] = 0.f;

    for (int kt = 0; kt < K; kt += KC) {
        // ---- load A tile [BM x KC] ----
        constexpr int LA = (BM * KC / 4) / 256;
        #pragma unroll
        for (int t = 0; t < LA; t++) {
            int i   = tid + t * 256;
            int row = i >> 3;                 // KC/4 == 8
            int c4  = (i & 7) * 4;
            int gr  = row0 + row;
            float4 v = make_float4(0.f, 0.f, 0.f, 0.f);
            if (gr < nrows) v = *(const float4*)&X[(size_t)gr * K + kt + c4];
            uint32_t* p = &sA[row * KCP + c4];
            p[0] = f2tf(v.x); p[1] = f2tf(v.y); p[2] = f2tf(v.z); p[3] = f2tf(v.w);
        }
        // ---- load W tile [KC x BN] ----
        constexpr int LB = (KC * BN / 4) / 256;
        #pragma unroll
        for (int t = 0; t < LB; t++) {
            int i   = tid + t * 256;
            int row = i / (BN / 4);
            int c4  = (i % (BN / 4)) * 4;
            float4 v = *(const float4*)&W[(size_t)(kt + row) * H + c0 + c4];
            uint32_t* p = &sB[row * BNP + c4];
            p[0] = f2tf(v.x); p[1] = f2tf(v.y); p[2] = f2tf(v.z); p[3] = f2tf(v.w);
        }
        __syncthreads();

        #pragma unroll
        for (int ks = 0; ks < KC / 8; ks++) {
            uint32_t a[2][4], b[4][2];
            int ar = wm * 32 + (lane >> 2);
            int ac = ks * 8 + (lane & 3);
            #pragma unroll
            for (int mi = 0; mi < 2; mi++) {
                int base = (ar + mi * 16) * KCP + ac;
                a[mi][0] = sA[base];
                a[mi][1] = sA[base + 8 * KCP];
                a[mi][2] = sA[base + 4];
                a[mi][3] = sA[base + 8 * KCP + 4];
            }
            int bk = ks * 8 + (lane & 3);
            int bc = wn * 32 + (lane >> 2);
            #pragma unroll
            for (int nj = 0; nj < 4; nj++) {
                int idx = bk * BNP + bc + nj * 8;
                b[nj][0] = sB[idx];
                b[nj][1] = sB[idx + 4 * BNP];
            }
            #pragma unroll
            for (int mi = 0; mi < 2; mi++)
                #pragma unroll
                for (int nj = 0; nj < 4; nj++)
                    mma_tf32(acc[mi][nj], a[mi], b[nj]);
        }
        __syncthreads();
    }

    // ---- epilogue ----
    const float rs = rsqrtf(1.f + 1e-5f);
    #pragma unroll
    for (int mi = 0; mi < 2; mi++) {
        #pragma unroll
        for (int hf = 0; hf < 2; hf++) {
            int gr = row0 + wm * 32 + mi * 16 + (lane >> 2) + hf * 8;
            if (gr >= nrows) continue;
            float ind = 1.f;
            if (EPI == 1) ind = (g_deg[gr] > 0) ? 1.f : 0.f;
            #pragma unroll
            for (int nj = 0; nj < 4; nj++) {
                int c = c0 + wn * 32 + nj * 8 + 2 * (lane & 3);
                float v0 = acc[mi][nj][hf * 2 + 0];
                float v1 = acc[mi][nj][hf * 2 + 1];
                if (EPI == 0) {
                    v0 += bias[c];
                    v1 += bias[c + 1];
                } else {
                    v0 = fmaxf(fmaf(v0 + bias[c]     * ind, gam[c]     * rs, bet[c]),     0.f);
                    v1 = fmaxf(fmaf(v1 + bias[c + 1] * ind, gam[c + 1] * rs, bet[c + 1]), 0.f);
                }
                *(float2*)&Y[(size_t)gr * H + c] = make_float2(v0, v1);
            }
        }
    }
}

// ---------------- edge aggregation: M[v] = mean_e relu(A[v]+B[src_e]) ------
template <int H>
__global__ void edge_agg_kernel(int n) {
    constexpr int VPL = H / 32;          // contiguous floats per lane
    int w    = (blockIdx.x * blockDim.x + threadIdx.x) >> 5;
    int lane = threadIdx.x & 31;
    if (w >= n) return;

    const float* Arow = g_AB + (size_t)w * (2 * H) + lane * VPL;
    float a[VPL], acc[VPL];
    if constexpr (VPL == 4) {
        float4 v = *(const float4*)Arow;
        a[0] = v.x; a[1] = v.y; a[2] = v.z; a[3] = v.w;
    } else if constexpr (VPL == 2) {
        float2 v = *(const float2*)Arow;
        a[0] = v.x; a[1] = v.y;
    } else {
        a[0] = Arow[0];
    }
    #pragma unroll
    for (int j = 0; j < VPL; j++) acc[j] = 0.f;

    int st = g_off[w];
    int d  = g_deg[w];
    for (int e = st; e < st + d; e++) {
        int s = g_srt_src[e];
        const float* Brow = g_AB + (size_t)s * (2 * H) + H + lane * VPL;
        if constexpr (VPL == 4) {
            float4 v = *(const float4*)Brow;
            acc[0] += fmaxf(a[0] + v.x, 0.f);
            acc[1] += fmaxf(a[1] + v.y, 0.f);
            acc[2] += fmaxf(a[2] + v.z, 0.f);
            acc[3] += fmaxf(a[3] + v.w, 0.f);
        } else if constexpr (VPL == 2) {
            float2 v = *(const float2*)Brow;
            acc[0] += fmaxf(a[0] + v.x, 0.f);
            acc[1] += fmaxf(a[1] + v.y, 0.f);
        } else {
            acc[0] += fmaxf(a[0] + Brow[0], 0.f);
        }
    }
    float inv = 1.f / (float)max(d, 1);
    #pragma unroll
    for (int j = 0; j < VPL; j++)
        g_M[(size_t)w * H + lane * VPL + j] = acc[j] * inv;
}

// ---------------- pooling + classifier ----------------
__global__ void pool_kernel(const int* __restrict__ batch, int n) {
    int i = blockIdx.x * blockDim.x + threadIdx.x;
    if (i >= n * 32) return;
    int v = i >> 5, c = i & 31;
    int b = batch[v];
    atomicAdd(&g_pool[b * 32 + c], g_h[(size_t)v * 32 + c]);
    if (c == 0) atomicAdd(&g_gcnt[b], 1.f);
}

__global__ void final_kernel(const float* __restrict__ Wfc,
                             const float* __restrict__ bfc,
                             float* __restrict__ out, int g) {
    int t = blockIdx.x * blockDim.x + threadIdx.x;
    if (t >= g * 5) return;
    int gi = t / 5, o = t % 5;
    float inv = 1.f / fmaxf(g_gcnt[gi], 1.f);
    float z = bfc[o];
    #pragma unroll
    for (int k = 0; k < 32; k++)
        z = fmaf(g_pool[gi * 32 + k] * inv, Wfc[k * 5 + o], z);
    out[t] = 1.f / (1.f + expf(-z));
}

// ---------------- launch ----------------
static inline int cdiv(int a, int b) { return (a + b - 1) / b; }

extern "C" void kernel_launch(void* const* d_in, const int* in_sizes, int n_in,
                              void* d_out, int out_size) {
    const float* x     = (const float*)d_in[0];
    const float* Wn    = (const float*)d_in[4];
    const float* bnode = (const float*)d_in[5];
    const float* W1a   = (const float*)d_in[6];
    const float* b1a   = (const float*)d_in[7];
    const float* W1b   = (const float*)d_in[8];
    const float* b1b   = (const float*)d_in[9];
    const float* W2a   = (const float*)d_in[10];
    const float* b2a   = (const float*)d_in[11];
    const float* W2b   = (const float*)d_in[12];
    const float* b2b   = (const float*)d_in[13];
    const float* W3a   = (const float*)d_in[14];
    const float* b3a   = (const float*)d_in[15];
    const float* W3b   = (const float*)d_in[16];
    const float* b3b   = (const float*)d_in[17];
    const float* gm1   = (const float*)d_in[18];
    const float* bt1   = (const float*)d_in[19];
    const float* gm2   = (const float*)d_in[20];
    const float* bt2   = (const float*)d_in[21];
    const float* gm3   = (const float*)d_in[22];
    const float* bt3   = (const float*)d_in[23];
    const float* Wfc   = (const float*)d_in[24];
    const float* bfc   = (const float*)d_in[25];
    const int*   ei    = (const int*)d_in[26];
    const int*   batch = (const int*)d_in[27];

    const int n = in_sizes[0] / 32;
    const int e = in_sizes[26] / 2;
    const int g = out_size / 5;

    const int* src = ei;
    const int* dst = ei + e;

    float *h, *M, *AB, *Wc1, *bc1, *Wc2, *bc2, *Wc3, *bc3;
    cudaGetSymbolAddress((void**)&h,   g_h);
    cudaGetSymbolAddress((void**)&M,   g_M);
    cudaGetSymbolAddress((void**)&AB,  g_AB);
    cudaGetSymbolAddress((void**)&Wc1, g_Wc1);
    cudaGetSymbolAddress((void**)&bc1, g_bc1);
    cudaGetSymbolAddress((void**)&Wc2, g_Wc2);
    cudaGetSymbolAddress((void**)&bc2, g_bc2);
    cudaGetSymbolAddress((void**)&Wc3, g_Wc3);
    cudaGetSymbolAddress((void**)&bc3, g_bc3);

    int zmax = max(n, g * 32);
    zero_kernel<<<cdiv(zmax, 256), 256>>>(n, g);
    hist_kernel<<<cdiv(e, 256), 256>>>(dst, e);
    alloc_kernel<<<cdiv(n, 256), 256>>>(n);
    scatter_kernel<<<cdiv(e, 256), 256>>>(src, dst, e);

    prep_kernel<<<64, 256>>>(W1a, b1a, Wc1, bc1, 64, 128);
    prep_kernel<<<64, 256>>>(W2a, b2a, Wc2, bc2, 128, 64);
    prep_kernel<<<64, 256>>>(W3a, b3a, Wc3, bc3, 64, 32);

    // h0 = x @ Wn + bnode           [N,64]
    mma_gemm<32, 64, 0><<<dim3(cdiv(n, 128), 1), 256>>>(x, Wn, h, bnode, nullptr, nullptr, n);

    // ---- layer 1 ----
    mma_gemm<64, 256, 0><<<dim3(cdiv(n, 128), 4), 256>>>(h, Wc1, AB, bc1, nullptr, nullptr, n);
    edge_agg_kernel<128><<<cdiv(n, 8), 256>>>(n);
    mma_gemm<128, 128, 1><<<dim3(cdiv(n, 128), 2), 256>>>(M, W1b, h, b1b, gm1, bt1, n);

    // ---- layer 2 ----
    mma_gemm<128, 128, 0><<<dim3(cdiv(n, 128), 2), 256>>>(h, Wc2, AB, bc2, nullptr, nullptr, n);
    edge_agg_kernel<64><<<cdiv(n, 8), 256>>>(n);
    mma_gemm<64, 64, 1><<<dim3(cdiv(n, 128), 1), 256>>>(M, W2b, h, b2b, gm2, bt2, n);

    // ---- layer 3 ----
    mma_gemm<64, 64, 0><<<dim3(cdiv(n, 128), 1), 256>>>(h, Wc3, AB, bc3, nullptr, nullptr, n);
    edge_agg_kernel<32><<<cdiv(n, 8), 256>>>(n);
    mma_gemm<32, 32, 1><<<dim3(cdiv(n, 256), 1), 256>>>(M, W3b, h, b3b, gm3, bt3, n);

    // ---- pool + classifier ----
    pool_kernel<<<cdiv(n * 32, 256), 256>>>(batch, n);
    final_kernel<<<cdiv(g * 5, 256), 256>>>(Wfc, bfc, (float*)d_out, g);
}

// round 4
// speedup vs baseline: 2.0955x; 1.0842x over previous
#include <cuda_runtime.h>
#include <cuda_bf16.h>
#include <math.h>
#include <stdint.h>

// ---------------- problem-size bounds ----------------
#define NMAX 50048
#define EMAX 600064
#define GMAX 2048

// ---------------- scratch (device globals) ----------------
__device__ int   g_deg[NMAX];
__device__ int   g_off[NMAX];
__device__ int   g_pos[NMAX];
__device__ int   g_total;
__device__ int   g_srt_src[EMAX];

__device__ float g_h [NMAX * 128];
__device__ float g_M [NMAX * 128];
__device__ __nv_bfloat16 g_AB[NMAX * 256];   // per-node [A | B], bf16

__device__ float g_Wc1[64 * 256],  g_bc1[256];
__device__ float g_Wc2[128 * 128], g_bc2[128];
__device__ float g_Wc3[64 * 64],   g_bc3[64];

__device__ float g_pool[GMAX * 32];
__device__ float g_gcnt[GMAX];

// ---------------- small utility kernels ----------------
__global__ void zero_kernel(int n, int g) {
    int i = blockIdx.x * blockDim.x + threadIdx.x;
    if (i == 0)     g_total   = 0;
    if (i < n)      g_deg[i]  = 0;
    if (i < g * 32) g_pool[i] = 0.f;
    if (i < g)      g_gcnt[i] = 0.f;
}

__global__ void hist_kernel(const int* __restrict__ dst, int e) {
    int i = blockIdx.x * blockDim.x + threadIdx.x;
    if (i < e) atomicAdd(&g_deg[dst[i]], 1);
}

// Warp-aggregated range allocation (order across nodes irrelevant for mean).
// Also accumulates per-graph node counts.
__global__ void alloc_kernel(int n, const int* __restrict__ batch) {
    int i = blockIdx.x * blockDim.x + threadIdx.x;
    int lane = threadIdx.x & 31;
    int d = (i < n) ? g_deg[i] : 0;
    int pre = d;
    #pragma unroll
    for (int s = 1; s < 32; s <<= 1) {
        int t = __shfl_up_sync(0xffffffffu, pre, s);
        if (lane >= s) pre += t;
    }
    int wsum = __shfl_sync(0xffffffffu, pre, 31);
    int base = 0;
    if (lane == 31) base = atomicAdd(&g_total, wsum);
    base = __shfl_sync(0xffffffffu, base, 31);
    int off = base + pre - d;
    if (i < n) {
        g_off[i] = off; g_pos[i] = off;
        atomicAdd(&g_gcnt[batch[i]], 1.f);
    }
}

__global__ void scatter_kernel(const int* __restrict__ src,
                               const int* __restrict__ dst, int e) {
    int i = blockIdx.x * blockDim.x + threadIdx.x;
    if (i < e) {
        int p = atomicAdd(&g_pos[dst[i]], 1);
        g_srt_src[p] = src[i];
    }
}

// Wc[D][2H]: cols [0,H) = Wtop - Wbot, [H,2H) = Wbot; bc: [b | 0].
__global__ void prep_kernel(const float* __restrict__ W, const float* __restrict__ b,
                            float* __restrict__ Wc, float* __restrict__ bc,
                            int D, int H) {
    int total = D * 2 * H;
    for (int i = blockIdx.x * blockDim.x + threadIdx.x; i < total;
         i += gridDim.x * blockDim.x) {
        int k = i / (2 * H), c = i % (2 * H);
        if (c < H) Wc[i] = W[k * H + c] - W[(k + D) * H + c];
        else       Wc[i] = W[(k + D) * H + (c - H)];
        if (i < 2 * H) bc[i] = (i < H) ? b[i] : 0.f;
    }
}

// ---------------- tf32 tensor-core GEMM ----------------
__device__ __forceinline__ uint32_t f2tf(float f) {
    uint32_t u;
    asm("cvt.rna.tf32.f32 %0, %1;" : "=r"(u) : "f"(f));
    return u;
}

__device__ __forceinline__ void mma_tf32(float* c, const uint32_t* a, const uint32_t* b) {
    asm volatile(
        "mma.sync.aligned.m16n8k8.row.col.f32.tf32.tf32.f32 "
        "{%0,%1,%2,%3}, {%4,%5,%6,%7}, {%8,%9}, {%0,%1,%2,%3};"
        : "+f"(c[0]), "+f"(c[1]), "+f"(c[2]), "+f"(c[3])
        : "r"(a[0]), "r"(a[1]), "r"(a[2]), "r"(a[3]), "r"(b[0]), "r"(b[1]));
}

// Y[N,H] = X[N,K] @ W[K,H]  (+ epilogue)
// EPI=0: fp32 out, Y = acc + bias[c]
// EPI=2: bf16 out, Y = acc + bias[c]
// EPI=1: fp32 out, Y = relu((acc + bias[c]*[deg>0]) * g[c]/sqrt(1+eps) + beta[c])
// EPI=3: EPI=1 + atomic pool accumulation (H must be 32)
template <int K, int H, int EPI>
__global__ __launch_bounds__(256)
void mma_gemm(const float* __restrict__ X, const float* __restrict__ W,
              void* __restrict__ Yv, const float* __restrict__ bias,
              const float* __restrict__ gam, const float* __restrict__ bet,
              const int* __restrict__ batch, int nrows) {
    constexpr int BN  = (H < 64) ? H : 64;
    constexpr int WN  = BN / 32;
    constexpr int WM  = 8 / WN;
    constexpr int BM  = WM * 32;
    constexpr int KC  = 32;
    constexpr int KCP = KC + 4;
    constexpr int BNP = BN + 8;

    __shared__ uint32_t sA[BM * KCP];
    __shared__ uint32_t sB[KC * BNP];

    const int tid  = threadIdx.x;
    const int lane = tid & 31;
    const int wid  = tid >> 5;
    const int wm   = wid % WM;
    const int wn   = wid / WM;
    const int row0 = blockIdx.x * BM;
    const int c0   = blockIdx.y * BN;

    float acc[2][4][4];
    #pragma unroll
    for (int mi = 0; mi < 2; mi++)
        #pragma unroll
        for (int nj = 0; nj < 4; nj++)
            #pragma unroll
            for (int q = 0; q < 4; q++) acc[mi][nj][q] = 0.f;

    for (int kt = 0; kt < K; kt += KC) {
        constexpr int LA = (BM * KC / 4) / 256;
        #pragma unroll
        for (int t = 0; t < LA; t++) {
            int i   = tid + t * 256;
            int row = i >> 3;
            int c4  = (i & 7) * 4;
            int gr  = row0 + row;
            float4 v = make_float4(0.f, 0.f, 0.f, 0.f);
            if (gr < nrows) v = *(const float4*)&X[(size_t)gr * K + kt + c4];
            uint32_t* p = &sA[row * KCP + c4];
            p[0] = f2tf(v.x); p[1] = f2tf(v.y); p[2] = f2tf(v.z); p[3] = f2tf(v.w);
        }
        constexpr int LB = (KC * BN / 4) / 256;
        #pragma unroll
        for (int t = 0; t < LB; t++) {
            int i   = tid + t * 256;
            int row = i / (BN / 4);
            int c4  = (i % (BN / 4)) * 4;
            float4 v = *(const float4*)&W[(size_t)(kt + row) * H + c0 + c4];
            uint32_t* p = &sB[row * BNP + c4];
            p[0] = f2tf(v.x); p[1] = f2tf(v.y); p[2] = f2tf(v.z); p[3] = f2tf(v.w);
        }
        __syncthreads();

        #pragma unroll
        for (int ks = 0; ks < KC / 8; ks++) {
            uint32_t a[2][4], b[4][2];
            int ar = wm * 32 + (lane >> 2);
            int ac = ks * 8 + (lane & 3);
            #pragma unroll
            for (int mi = 0; mi < 2; mi++) {
                int base = (ar + mi * 16) * KCP + ac;
                a[mi][0] = sA[base];
                a[mi][1] = sA[base + 8 * KCP];
                a[mi][2] = sA[base + 4];
                a[mi][3] = sA[base + 8 * KCP + 4];
            }
            int bk = ks * 8 + (lane & 3);
            int bc = wn * 32 + (lane >> 2);
            #pragma unroll
            for (int nj = 0; nj < 4; nj++) {
                int idx = bk * BNP + bc + nj * 8;
                b[nj][0] = sB[idx];
                b[nj][1] = sB[idx + 4 * BNP];
            }
            #pragma unroll
            for (int mi = 0; mi < 2; mi++)
                #pragma unroll
                for (int nj = 0; nj < 4; nj++)
                    mma_tf32(acc[mi][nj], a[mi], b[nj]);
        }
        __syncthreads();
    }

    // ---- epilogue ----
    const float rs = rsqrtf(1.f + 1e-5f);
    float* Yf = (float*)Yv;
    __nv_bfloat16* Yb = (__nv_bfloat16*)Yv;
    #pragma unroll
    for (int mi = 0; mi < 2; mi++) {
        #pragma unroll
        for (int hf = 0; hf < 2; hf++) {
            int gr = row0 + wm * 32 + mi * 16 + (lane >> 2) + hf * 8;
            if (gr >= nrows) continue;
            float ind = 1.f;
            if (EPI == 1 || EPI == 3) ind = (g_deg[gr] > 0) ? 1.f : 0.f;
            int pb = 0;
            if (EPI == 3) pb = batch[gr] * 32;
            #pragma unroll
            for (int nj = 0; nj < 4; nj++) {
                int c = c0 + wn * 32 + nj * 8 + 2 * (lane & 3);
                float v0 = acc[mi][nj][hf * 2 + 0];
                float v1 = acc[mi][nj][hf * 2 + 1];
                if (EPI == 0 || EPI == 2) {
                    v0 += bias[c];
                    v1 += bias[c + 1];
                } else {
                    v0 = fmaxf(fmaf(v0 + bias[c]     * ind, gam[c]     * rs, bet[c]),     0.f);
                    v1 = fmaxf(fmaf(v1 + bias[c + 1] * ind, gam[c + 1] * rs, bet[c + 1]), 0.f);
                }
                if (EPI == 2) {
                    __nv_bfloat162 p = __floats2bfloat162_rn(v0, v1);
                    *(__nv_bfloat162*)&Yb[(size_t)gr * H + c] = p;
                } else {
                    *(float2*)&Yf[(size_t)gr * H + c] = make_float2(v0, v1);
                    if (EPI == 3) {
                        atomicAdd(&g_pool[pb + c],     v0);
                        atomicAdd(&g_pool[pb + c + 1], v1);
                    }
                }
            }
        }
    }
}

// ------- edge aggregation: M[v] = mean_e relu(A[v]+B[src_e]), bf16 AB -------
// Each lane owns 4 bf16 (8 bytes); LPN = H/4 lanes per node.
template <int H>
__global__ void edge_agg_kernel(int n) {
    constexpr int LPN = H / 4;
    constexpr int NPW = 32 / LPN;
    int gw   = (blockIdx.x * blockDim.x + threadIdx.x) >> 5;
    int lane = threadIdx.x & 31;
    int sub  = lane / LPN;
    int sl   = lane % LPN;
    int w    = gw * NPW + sub;
    if (w >= n) return;

    const __nv_bfloat16* ABp = g_AB;
    uint2 av = *(const uint2*)(ABp + (size_t)w * 2 * H + sl * 4);
    float2 a01 = __bfloat1622float2(*(__nv_bfloat162*)&av.x);
    float2 a23 = __bfloat1622float2(*(__nv_bfloat162*)&av.y);

    float acc0 = 0.f, acc1 = 0.f, acc2 = 0.f, acc3 = 0.f;

    int st = g_off[w];
    int d  = g_deg[w];
    int en = st + d;
    int e  = st;

    for (; e + 4 <= en; e += 4) {
        int s0 = g_srt_src[e];
        int s1 = g_srt_src[e + 1];
        int s2 = g_srt_src[e + 2];
        int s3 = g_srt_src[e + 3];
        uint2 b0 = *(const uint2*)(ABp + (size_t)s0 * 2 * H + H + sl * 4);
        uint2 b1 = *(const uint2*)(ABp + (size_t)s1 * 2 * H + H + sl * 4);
        uint2 b2 = *(const uint2*)(ABp + (size_t)s2 * 2 * H + H + sl * 4);
        uint2 b3 = *(const uint2*)(ABp + (size_t)s3 * 2 * H + H + sl * 4);
        #pragma unroll
        for (int q = 0; q < 4; q++) {
            uint2 bq = (q == 0) ? b0 : (q == 1) ? b1 : (q == 2) ? b2 : b3;
            float2 x01 = __bfloat1622float2(*(__nv_bfloat162*)&bq.x);
            float2 x23 = __bfloat1622float2(*(__nv_bfloat162*)&bq.y);
            acc0 += fmaxf(a01.x + x01.x, 0.f);
            acc1 += fmaxf(a01.y + x01.y, 0.f);
            acc2 += fmaxf(a23.x + x23.x, 0.f);
            acc3 += fmaxf(a23.y + x23.y, 0.f);
        }
    }
    for (; e < en; e++) {
        int s = g_srt_src[e];
        uint2 bq = *(const uint2*)(ABp + (size_t)s * 2 * H + H + sl * 4);
        float2 x01 = __bfloat1622float2(*(__nv_bfloat162*)&bq.x);
        float2 x23 = __bfloat1622float2(*(__nv_bfloat162*)&bq.y);
        acc0 += fmaxf(a01.x + x01.x, 0.f);
        acc1 += fmaxf(a01.y + x01.y, 0.f);
        acc2 += fmaxf(a23.x + x23.x, 0.f);
        acc3 += fmaxf(a23.y + x23.y, 0.f);
    }

    float inv = 1.f / (float)max(d, 1);
    float4 out = make_float4(acc0 * inv, acc1 * inv, acc2 * inv, acc3 * inv);
    *(float4*)&g_M[(size_t)w * H + sl * 4] = out;
}

// ---------------- classifier ----------------
__global__ void final_kernel(const float* __restrict__ Wfc,
                             const float* __restrict__ bfc,
                             float* __restrict__ out, int g) {
    int t = blockIdx.x * blockDim.x + threadIdx.x;
    if (t >= g * 5) return;
    int gi = t / 5, o = t % 5;
    float inv = 1.f / fmaxf(g_gcnt[gi], 1.f);
    float z = bfc[o];
    #pragma unroll
    for (int k = 0; k < 32; k++)
        z = fmaf(g_pool[gi * 32 + k] * inv, Wfc[k * 5 + o], z);
    out[t] = 1.f / (1.f + expf(-z));
}

// ---------------- launch ----------------
static inline int cdiv(int a, int b) { return (a + b - 1) / b; }

extern "C" void kernel_launch(void* const* d_in, const int* in_sizes, int n_in,
                              void* d_out, int out_size) {
    const float* x     = (const float*)d_in[0];
    const float* Wn    = (const float*)d_in[4];
    const float* bnode = (const float*)d_in[5];
    const float* W1a   = (const float*)d_in[6];
    const float* b1a   = (const float*)d_in[7];
    const float* W1b   = (const float*)d_in[8];
    const float* b1b   = (const float*)d_in[9];
    const float* W2a   = (const float*)d_in[10];
    const float* b2a   = (const float*)d_in[11];
    const float* W2b   = (const float*)d_in[12];
    const float* b2b   = (const float*)d_in[13];
    const float* W3a   = (const float*)d_in[14];
    const float* b3a   = (const float*)d_in[15];
    const float* W3b   = (const float*)d_in[16];
    const float* b3b   = (const float*)d_in[17];
    const float* gm1   = (const float*)d_in[18];
    const float* bt1   = (const float*)d_in[19];
    const float* gm2   = (const float*)d_in[20];
    const float* bt2   = (const float*)d_in[21];
    const float* gm3   = (const float*)d_in[22];
    const float* bt3   = (const float*)d_in[23];
    const float* Wfc   = (const float*)d_in[24];
    const float* bfc   = (const float*)d_in[25];
    const int*   ei    = (const int*)d_in[26];
    const int*   batch = (const int*)d_in[27];

    const int n = in_sizes[0] / 32;
    const int e = in_sizes[26] / 2;
    const int g = out_size / 5;

    const int* src = ei;
    const int* dst = ei + e;

    float *h, *M, *Wc1, *bc1, *Wc2, *bc2, *Wc3, *bc3;
    __nv_bfloat16* AB;
    cudaGetSymbolAddress((void**)&h,   g_h);
    cudaGetSymbolAddress((void**)&M,   g_M);
    cudaGetSymbolAddress((void**)&AB,  g_AB);
    cudaGetSymbolAddress((void**)&Wc1, g_Wc1);
    cudaGetSymbolAddress((void**)&bc1, g_bc1);
    cudaGetSymbolAddress((void**)&Wc2, g_Wc2);
    cudaGetSymbolAddress((void**)&bc2, g_bc2);
    cudaGetSymbolAddress((void**)&Wc3, g_Wc3);
    cudaGetSymbolAddress((void**)&bc3, g_bc3);

    int zmax = max(n, g * 32);
    zero_kernel<<<cdiv(zmax, 256), 256>>>(n, g);
    hist_kernel<<<cdiv(e, 256), 256>>>(dst, e);
    alloc_kernel<<<cdiv(n, 256), 256>>>(n, batch);
    scatter_kernel<<<cdiv(e, 256), 256>>>(src, dst, e);

    prep_kernel<<<64, 256>>>(W1a, b1a, Wc1, bc1, 64, 128);
    prep_kernel<<<64, 256>>>(W2a, b2a, Wc2, bc2, 128, 64);
    prep_kernel<<<64, 256>>>(W3a, b3a, Wc3, bc3, 64, 32);

    // h0 = x @ Wn + bnode           [N,64] fp32
    mma_gemm<32, 64, 0><<<dim3(cdiv(n, 128), 1), 256>>>(x, Wn, h, bnode, nullptr, nullptr, nullptr, n);

    // ---- layer 1 ----
    mma_gemm<64, 256, 2><<<dim3(cdiv(n, 128), 4), 256>>>(h, Wc1, AB, bc1, nullptr, nullptr, nullptr, n);
    edge_agg_kernel<128><<<cdiv(n, 8), 256>>>(n);
    mma_gemm<128, 128, 1><<<dim3(cdiv(n, 128), 2), 256>>>(M, W1b, h, b1b, gm1, bt1, nullptr, n);

    // ---- layer 2 ----
    mma_gemm<128, 128, 2><<<dim3(cdiv(n, 128), 2), 256>>>(h, Wc2, AB, bc2, nullptr, nullptr, nullptr, n);
    edge_agg_kernel<64><<<cdiv(n, 16), 256>>>(n);
    mma_gemm<64, 64, 1><<<dim3(cdiv(n, 128), 1), 256>>>(M, W2b, h, b2b, gm2, bt2, nullptr, n);

    // ---- layer 3 ----
    mma_gemm<64, 64, 2><<<dim3(cdiv(n, 128), 1), 256>>>(h, Wc3, AB, bc3, nullptr, nullptr, nullptr, n);
    edge_agg_kernel<32><<<cdiv(n, 32), 256>>>(n);
    mma_gemm<32, 32, 3><<<dim3(cdiv(n, 256), 1), 256>>>(M, W3b, h, b3b, gm3, bt3, batch, n);

    // ---- classifier ----
    final_kernel<<<cdiv(g * 5, 256), 256>>>(Wfc, bfc, (float*)d_out, g);
}

// round 5
// speedup vs baseline: 2.4470x; 1.1678x over previous
#include <cuda_runtime.h>
#include <cuda_bf16.h>
#include <math.h>
#include <stdint.h>

// ---------------- problem-size bounds ----------------
#define NMAX 50048
#define EMAX 600064
#define GMAX 2048

typedef __nv_bfloat16 bf16;
typedef __nv_bfloat162 bf162;

// ---------------- scratch (device globals) ----------------
__device__ int   g_deg[NMAX];
__device__ int   g_off[NMAX];
__device__ int   g_pos[NMAX];
__device__ int   g_total;
__device__ int   g_srt_src[EMAX];

__device__ bf16  g_Xb[NMAX * 32];
__device__ bf16  g_h [NMAX * 128];
__device__ bf16  g_M [NMAX * 128];
__device__ bf16  g_AB[NMAX * 256];

// bf16 weights, transposed to [H][K] (n-major)
__device__ bf16  g_Wtn [64 * 32];
__device__ bf16  g_Wct1[256 * 64];
__device__ bf16  g_Wt1b[128 * 128];
__device__ bf16  g_Wct2[128 * 128];
__device__ bf16  g_Wt2b[64 * 64];
__device__ bf16  g_Wct3[64 * 64];
__device__ bf16  g_Wt3b[32 * 32];
__device__ float g_bc1[256], g_bc2[128], g_bc3[64];

__device__ float g_pool[GMAX * 32];
__device__ float g_gcnt[GMAX];

// ---------------- init: zero counters + convert x to bf16 ----------------
__global__ void init_kernel(const float* __restrict__ x, int n, int g) {
    int i = blockIdx.x * blockDim.x + threadIdx.x;
    if (i == 0)      g_total   = 0;
    if (i < n)       g_deg[i]  = 0;
    if (i < g * 32)  g_pool[i] = 0.f;
    if (i < g)       g_gcnt[i] = 0.f;
    if (i < n * 32)  g_Xb[i]   = __float2bfloat16(x[i]);
}

__global__ void hist_kernel(const int* __restrict__ dst, int e) {
    int i = blockIdx.x * blockDim.x + threadIdx.x;
    if (i < e) atomicAdd(&g_deg[dst[i]], 1);
}

// Warp-aggregated range allocation + per-graph node counts.
__global__ void alloc_kernel(int n, const int* __restrict__ batch) {
    int i = blockIdx.x * blockDim.x + threadIdx.x;
    int lane = threadIdx.x & 31;
    int d = (i < n) ? g_deg[i] : 0;
    int pre = d;
    #pragma unroll
    for (int s = 1; s < 32; s <<= 1) {
        int t = __shfl_up_sync(0xffffffffu, pre, s);
        if (lane >= s) pre += t;
    }
    int wsum = __shfl_sync(0xffffffffu, pre, 31);
    int base = 0;
    if (lane == 31) base = atomicAdd(&g_total, wsum);
    base = __shfl_sync(0xffffffffu, base, 31);
    int off = base + pre - d;
    if (i < n) {
        g_off[i] = off; g_pos[i] = off;
        atomicAdd(&g_gcnt[batch[i]], 1.f);
    }
}

__global__ void scatter_kernel(const int* __restrict__ src,
                               const int* __restrict__ dst, int e) {
    int i = blockIdx.x * blockDim.x + threadIdx.x;
    if (i < e) {
        int p = atomicAdd(&g_pos[dst[i]], 1);
        g_srt_src[p] = src[i];
    }
}

// ---------------- single-launch weight prep ----------------
// Builds all bf16 transposed weights:
//  plain:    Wt[c][K] from W[K][H]  (Wt[c*K+k] = W[k*H+c])
//  combined: Wct[2H][D] from W[2D][H]; bc = [b | 0]
__global__ void prep_weights(const float* Wn,  const float* W1a, const float* b1a,
                             const float* W1b, const float* W2a, const float* b2a,
                             const float* W2b, const float* W3a, const float* b3a,
                             const float* W3b) {
    const int S0 = 64 * 32;        // Wtn
    const int S1 = 256 * 64;       // Wct1
    const int S2 = 128 * 128;      // Wt1b
    const int S3 = 128 * 128;      // Wct2
    const int S4 = 64 * 64;        // Wt2b
    const int S5 = 64 * 64;        // Wct3
    const int S6 = 32 * 32;        // Wt3b
    const int TOT = S0 + S1 + S2 + S3 + S4 + S5 + S6;
    for (int i = blockIdx.x * blockDim.x + threadIdx.x; i < TOT;
         i += gridDim.x * blockDim.x) {
        int j = i;
        if (j < S0) {                     // Wtn: K=32,H=64
            int c = j / 32, k = j % 32;
            g_Wtn[j] = __float2bfloat16(Wn[k * 64 + c]);
            continue;
        } j -= S0;
        if (j < S1) {                     // Wct1: D=64,H=128 -> [256][64]
            int c = j / 64, k = j % 64;
            float v = (c < 128) ? W1a[k * 128 + c] - W1a[(k + 64) * 128 + c]
                                : W1a[(k + 64) * 128 + (c - 128)];
            g_Wct1[j] = __float2bfloat16(v);
            if (k == 0) g_bc1[c] = (c < 128) ? b1a[c] : 0.f;
            continue;
        } j -= S1;
        if (j < S2) {                     // Wt1b: K=128,H=128
            int c = j / 128, k = j % 128;
            g_Wt1b[j] = __float2bfloat16(W1b[k * 128 + c]);
            continue;
        } j -= S2;
        if (j < S3) {                     // Wct2: D=128,H=64 -> [128][128]
            int c = j / 128, k = j % 128;
            float v = (c < 64) ? W2a[k * 64 + c] - W2a[(k + 128) * 64 + c]
                               : W2a[(k + 128) * 64 + (c - 64)];
            g_Wct2[j] = __float2bfloat16(v);
            if (k == 0) g_bc2[c] = (c < 64) ? b2a[c] : 0.f;
            continue;
        } j -= S3;
        if (j < S4) {                     // Wt2b: K=64,H=64
            int c = j / 64, k = j % 64;
            g_Wt2b[j] = __float2bfloat16(W2b[k * 64 + c]);
            continue;
        } j -= S4;
        if (j < S5) {                     // Wct3: D=64,H=32 -> [64][64]
            int c = j / 64, k = j % 64;
            float v = (c < 32) ? W3a[k * 32 + c] - W3a[(k + 64) * 32 + c]
                               : W3a[(k + 64) * 32 + (c - 32)];
            g_Wct3[j] = __float2bfloat16(v);
            if (k == 0) g_bc3[c] = (c < 32) ? b3a[c] : 0.f;
            continue;
        } j -= S5;
        {                                 // Wt3b: K=32,H=32
            int c = j / 32, k = j % 32;
            g_Wt3b[j] = __float2bfloat16(W3b[k * 32 + c]);
        }
    }
}

// ---------------- bf16 tensor-core GEMM (m16n8k16) ----------------
__device__ __forceinline__ void mma_bf16(float* c, const uint32_t* a, const uint32_t* b) {
    asm volatile(
        "mma.sync.aligned.m16n8k16.row.col.f32.bf16.bf16.f32 "
        "{%0,%1,%2,%3}, {%4,%5,%6,%7}, {%8,%9}, {%0,%1,%2,%3};"
        : "+f"(c[0]), "+f"(c[1]), "+f"(c[2]), "+f"(c[3])
        : "r"(a[0]), "r"(a[1]), "r"(a[2]), "r"(a[3]), "r"(b[0]), "r"(b[1]));
}

// Y[N,H] = X[N,K] @ Wt[H,K]^T  (+ epilogue). X, Wt bf16; acc fp32.
// EPI=0: bf16 out, Y = acc + bias[c]
// EPI=1: bf16 out, Y = relu((acc + bias[c]*[deg>0]) * gam[c]/sqrt(1+eps) + bet[c])
// EPI=3: EPI=1 value -> atomic pool only, no store (H must be 32)
template <int K, int H, int EPI>
__global__ __launch_bounds__(256)
void mma_gemm(const bf16* __restrict__ X, const bf16* __restrict__ Wt,
              bf16* __restrict__ Y, const float* __restrict__ bias,
              const float* __restrict__ gam, const float* __restrict__ bet,
              const int* __restrict__ batch, int nrows) {
    constexpr int BN = (H < 64) ? H : 64;
    constexpr int WN = BN / 32;
    constexpr int WM = 8 / WN;
    constexpr int BM = WM * 32;
    constexpr int RS = 20;                 // uint32 row stride (16 data + 4 pad)

    __shared__ uint32_t sA[BM * RS];
    __shared__ uint32_t sB[BN * RS];

    const int tid  = threadIdx.x;
    const int lane = tid & 31;
    const int wid  = tid >> 5;
    const int wm   = wid % WM;
    const int wn   = wid / WM;
    const int row0 = blockIdx.x * BM;
    const int c0   = blockIdx.y * BN;
    const int gq   = lane >> 2;
    const int t4   = lane & 3;

    float acc[2][4][4];
    #pragma unroll
    for (int mi = 0; mi < 2; mi++)
        #pragma unroll
        for (int nj = 0; nj < 4; nj++)
            #pragma unroll
            for (int q = 0; q < 4; q++) acc[mi][nj][q] = 0.f;

    for (int kt = 0; kt < K; kt += 32) {
        // A tile: BM x 32 bf16, uint4 = 8 bf16 per load
        #pragma unroll
        for (int t = 0; t < BM / 64; t++) {
            int i   = tid + t * 256;
            int row = i >> 2, q = i & 3;
            int gr  = row0 + row;
            uint4 v = make_uint4(0u, 0u, 0u, 0u);
            if (gr < nrows) v = *(const uint4*)&X[(size_t)gr * K + kt + q * 8];
            *(uint4*)&sA[row * RS + q * 4] = v;
        }
        // B tile: BN x 32 bf16 (from pre-transposed Wt[H][K])
        if (tid < BN * 4) {
            int row = tid >> 2, q = tid & 3;
            *(uint4*)&sB[row * RS + q * 4] =
                *(const uint4*)&Wt[(size_t)(c0 + row) * K + kt + q * 8];
        }
        __syncthreads();

        #pragma unroll
        for (int ks = 0; ks < 2; ks++) {
            uint32_t a[2][4], b[4][2];
            #pragma unroll
            for (int mi = 0; mi < 2; mi++) {
                int r = wm * 32 + mi * 16 + gq;
                a[mi][0] = sA[r * RS + ks * 8 + t4];
                a[mi][1] = sA[(r + 8) * RS + ks * 8 + t4];
                a[mi][2] = sA[r * RS + ks * 8 + t4 + 4];
                a[mi][3] = sA[(r + 8) * RS + ks * 8 + t4 + 4];
            }
            #pragma unroll
            for (int nj = 0; nj < 4; nj++) {
                int nr = wn * 32 + nj * 8 + gq;
                b[nj][0] = sB[nr * RS + ks * 8 + t4];
                b[nj][1] = sB[nr * RS + ks * 8 + t4 + 4];
            }
            #pragma unroll
            for (int mi = 0; mi < 2; mi++)
                #pragma unroll
                for (int nj = 0; nj < 4; nj++)
                    mma_bf16(acc[mi][nj], a[mi], b[nj]);
        }
        __syncthreads();
    }

    // ---- epilogue ----
    const float rs = rsqrtf(1.f + 1e-5f);
    #pragma unroll
    for (int mi = 0; mi < 2; mi++) {
        #pragma unroll
        for (int hf = 0; hf < 2; hf++) {
            int gr = row0 + wm * 32 + mi * 16 + gq + hf * 8;
            if (gr >= nrows) continue;
            float ind = 1.f;
            if (EPI == 1 || EPI == 3) ind = (g_deg[gr] > 0) ? 1.f : 0.f;
            int pb = 0;
            if (EPI == 3) pb = batch[gr] * 32;
            #pragma unroll
            for (int nj = 0; nj < 4; nj++) {
                int c = c0 + wn * 32 + nj * 8 + 2 * t4;
                float v0 = acc[mi][nj][hf * 2 + 0];
                float v1 = acc[mi][nj][hf * 2 + 1];
                if (EPI == 0) {
                    v0 += bias[c];
                    v1 += bias[c + 1];
                } else {
                    v0 = fmaxf(fmaf(v0 + bias[c]     * ind, gam[c]     * rs, bet[c]),     0.f);
                    v1 = fmaxf(fmaf(v1 + bias[c + 1] * ind, gam[c + 1] * rs, bet[c + 1]), 0.f);
                }
                if (EPI == 3) {
                    atomicAdd(&g_pool[pb + c],     v0);
                    atomicAdd(&g_pool[pb + c + 1], v1);
                } else {
                    bf162 p = __floats2bfloat162_rn(v0, v1);
                    *(bf162*)&Y[(size_t)gr * H + c] = p;
                }
            }
        }
    }
}

// ------- edge aggregation: M[v] = mean_e relu(A[v]+B[src_e]); AB,M bf16 -----
template <int H>
__global__ void edge_agg_kernel(int n) {
    constexpr int LPN = H / 4;
    constexpr int NPW = 32 / LPN;
    int gw   = (blockIdx.x * blockDim.x + threadIdx.x) >> 5;
    int lane = threadIdx.x & 31;
    int sub  = lane / LPN;
    int sl   = lane % LPN;
    int w    = gw * NPW + sub;
    if (w >= n) return;

    const bf16* ABp = g_AB;
    uint2 av = *(const uint2*)(ABp + (size_t)w * 2 * H + sl * 4);
    float2 a01 = __bfloat1622float2(*(bf162*)&av.x);
    float2 a23 = __bfloat1622float2(*(bf162*)&av.y);

    float acc0 = 0.f, acc1 = 0.f, acc2 = 0.f, acc3 = 0.f;

    int st = g_off[w];
    int d  = g_deg[w];
    int en = st + d;
    int e  = st;

    for (; e + 4 <= en; e += 4) {
        int s0 = g_srt_src[e];
        int s1 = g_srt_src[e + 1];
        int s2 = g_srt_src[e + 2];
        int s3 = g_srt_src[e + 3];
        uint2 b0 = *(const uint2*)(ABp + (size_t)s0 * 2 * H + H + sl * 4);
        uint2 b1 = *(const uint2*)(ABp + (size_t)s1 * 2 * H + H + sl * 4);
        uint2 b2 = *(const uint2*)(ABp + (size_t)s2 * 2 * H + H + sl * 4);
        uint2 b3 = *(const uint2*)(ABp + (size_t)s3 * 2 * H + H + sl * 4);
        #pragma unroll
        for (int q = 0; q < 4; q++) {
            uint2 bq = (q == 0) ? b0 : (q == 1) ? b1 : (q == 2) ? b2 : b3;
            float2 x01 = __bfloat1622float2(*(bf162*)&bq.x);
            float2 x23 = __bfloat1622float2(*(bf162*)&bq.y);
            acc0 += fmaxf(a01.x + x01.x, 0.f);
            acc1 += fmaxf(a01.y + x01.y, 0.f);
            acc2 += fmaxf(a23.x + x23.x, 0.f);
            acc3 += fmaxf(a23.y + x23.y, 0.f);
        }
    }
    for (; e < en; e++) {
        int s = g_srt_src[e];
        uint2 bq = *(const uint2*)(ABp + (size_t)s * 2 * H + H + sl * 4);
        float2 x01 = __bfloat1622float2(*(bf162*)&bq.x);
        float2 x23 = __bfloat1622float2(*(bf162*)&bq.y);
        acc0 += fmaxf(a01.x + x01.x, 0.f);
        acc1 += fmaxf(a01.y + x01.y, 0.f);
        acc2 += fmaxf(a23.x + x23.x, 0.f);
        acc3 += fmaxf(a23.y + x23.y, 0.f);
    }

    float inv = 1.f / (float)max(d, 1);
    bf162 o01 = __floats2bfloat162_rn(acc0 * inv, acc1 * inv);
    bf162 o23 = __floats2bfloat162_rn(acc2 * inv, acc3 * inv);
    uint2 ov;
    ov.x = *(uint32_t*)&o01;
    ov.y = *(uint32_t*)&o23;
    *(uint2*)&g_M[(size_t)w * H + sl * 4] = ov;
}

// ---------------- classifier ----------------
__global__ void final_kernel(const float* __restrict__ Wfc,
                             const float* __restrict__ bfc,
                             float* __restrict__ out, int g) {
    int t = blockIdx.x * blockDim.x + threadIdx.x;
    if (t >= g * 5) return;
    int gi = t / 5, o = t % 5;
    float inv = 1.f / fmaxf(g_gcnt[gi], 1.f);
    float z = bfc[o];
    #pragma unroll
    for (int k = 0; k < 32; k++)
        z = fmaf(g_pool[gi * 32 + k] * inv, Wfc[k * 5 + o], z);
    out[t] = 1.f / (1.f + expf(-z));
}

// ---------------- launch ----------------
static inline int cdiv(int a, int b) { return (a + b - 1) / b; }

extern "C" void kernel_launch(void* const* d_in, const int* in_sizes, int n_in,
                              void* d_out, int out_size) {
    const float* x     = (const float*)d_in[0];
    const float* Wn    = (const float*)d_in[4];
    const float* bnode = (const float*)d_in[5];
    const float* W1a   = (const float*)d_in[6];
    const float* b1a   = (const float*)d_in[7];
    const float* W1b   = (const float*)d_in[8];
    const float* b1b   = (const float*)d_in[9];
    const float* W2a   = (const float*)d_in[10];
    const float* b2a   = (const float*)d_in[11];
    const float* W2b   = (const float*)d_in[12];
    const float* b2b   = (const float*)d_in[13];
    const float* W3a   = (const float*)d_in[14];
    const float* b3a   = (const float*)d_in[15];
    const float* W3b   = (const float*)d_in[16];
    const float* b3b   = (const float*)d_in[17];
    const float* gm1   = (const float*)d_in[18];
    const float* bt1   = (const float*)d_in[19];
    const float* gm2   = (const float*)d_in[20];
    const float* bt2   = (const float*)d_in[21];
    const float* gm3   = (const float*)d_in[22];
    const float* bt3   = (const float*)d_in[23];
    const float* Wfc   = (const float*)d_in[24];
    const float* bfc   = (const float*)d_in[25];
    const int*   ei    = (const int*)d_in[26];
    const int*   batch = (const int*)d_in[27];

    const int n = in_sizes[0] / 32;
    const int e = in_sizes[26] / 2;
    const int g = out_size / 5;

    const int* src = ei;
    const int* dst = ei + e;

    bf16 *Xb, *h, *M, *AB, *Wtn, *Wct1, *Wt1b, *Wct2, *Wt2b, *Wct3, *Wt3b;
    float *bc1, *bc2, *bc3;
    cudaGetSymbolAddress((void**)&Xb,   g_Xb);
    cudaGetSymbolAddress((void**)&h,    g_h);
    cudaGetSymbolAddress((void**)&M,    g_M);
    cudaGetSymbolAddress((void**)&AB,   g_AB);
    cudaGetSymbolAddress((void**)&Wtn,  g_Wtn);
    cudaGetSymbolAddress((void**)&Wct1, g_Wct1);
    cudaGetSymbolAddress((void**)&Wt1b, g_Wt1b);
    cudaGetSymbolAddress((void**)&Wct2, g_Wct2);
    cudaGetSymbolAddress((void**)&Wt2b, g_Wt2b);
    cudaGetSymbolAddress((void**)&Wct3, g_Wct3);
    cudaGetSymbolAddress((void**)&Wt3b, g_Wt3b);
    cudaGetSymbolAddress((void**)&bc1,  g_bc1);
    cudaGetSymbolAddress((void**)&bc2,  g_bc2);
    cudaGetSymbolAddress((void**)&bc3,  g_bc3);

    init_kernel<<<cdiv(n * 32, 256), 256>>>(x, n, g);
    hist_kernel<<<cdiv(e, 256), 256>>>(dst, e);
    alloc_kernel<<<cdiv(n, 256), 256>>>(n, batch);
    scatter_kernel<<<cdiv(e, 256), 256>>>(src, dst, e);
    prep_weights<<<236, 256>>>(Wn, W1a, b1a, W1b, W2a, b2a, W2b, W3a, b3a, W3b);

    // h0 = x @ Wn + bnode   [N,64] bf16
    mma_gemm<32, 64, 0><<<dim3(cdiv(n, 128), 1), 256>>>(Xb, Wtn, h, bnode, nullptr, nullptr, nullptr, n);

    // ---- layer 1 ----
    mma_gemm<64, 256, 0><<<dim3(cdiv(n, 128), 4), 256>>>(h, Wct1, AB, bc1, nullptr, nullptr, nullptr, n);
    edge_agg_kernel<128><<<cdiv(n, 8), 256>>>(n);
    mma_gemm<128, 128, 1><<<dim3(cdiv(n, 128), 2), 256>>>(M, Wt1b, h, b1b, gm1, bt1, nullptr, n);

    // ---- layer 2 ----
    mma_gemm<128, 128, 0><<<dim3(cdiv(n, 128), 2), 256>>>(h, Wct2, AB, bc2, nullptr, nullptr, nullptr, n);
    edge_agg_kernel<64><<<cdiv(n, 16), 256>>>(n);
    mma_gemm<64, 64, 1><<<dim3(cdiv(n, 128), 1), 256>>>(M, Wt2b, h, b2b, gm2, bt2, nullptr, n);

    // ---- layer 3 ----
    mma_gemm<64, 64, 0><<<dim3(cdiv(n, 128), 1), 256>>>(h, Wct3, AB, bc3, nullptr, nullptr, nullptr, n);
    edge_agg_kernel<32><<<cdiv(n, 32), 256>>>(n);
    mma_gemm<32, 32, 3><<<dim3(cdiv(n, 256), 1), 256>>>(M, Wt3b, nullptr, b3b, gm3, bt3, batch, n);

    // ---- classifier ----
    final_kernel<<<cdiv(g * 5, 256), 256>>>(Wfc, bfc, (float*)d_out, g);
}

// round 6
// speedup vs baseline: 2.8273x; 1.1554x over previous
#include <cuda_runtime.h>
#include <cuda_bf16.h>
#include <cuda_fp16.h>
#include <math.h>
#include <stdint.h>

// ---------------- problem-size bounds ----------------
#define NMAX 50048
#define EMAX 600064
#define GMAX 2048

typedef __nv_bfloat16 bf16;
typedef __nv_bfloat162 bf162;

// ---------------- scratch (device globals) ----------------
__device__ int   g_deg[NMAX];
__device__ int   g_off[NMAX];
__device__ int   g_pos[NMAX];
__device__ int   g_total;
__device__ int   g_srt_src[EMAX];

__device__ bf16    g_Xb[NMAX * 32];
__device__ bf16    g_M [NMAX * 128];
__device__ uint8_t g_AB[NMAX * 256];     // fp8 e4m3, per-node [A | B]

// bf16 weights, transposed to [H][K] (n-major)
__device__ bf16  g_Wtn [64 * 32];
__device__ bf16  g_Wct1[256 * 64];
__device__ bf16  g_Wt1b[128 * 128];
__device__ bf16  g_Wct2[128 * 128];
__device__ bf16  g_Wt2b[64 * 64];
__device__ bf16  g_Wct3[64 * 64];
__device__ bf16  g_Wt3b[32 * 32];
__device__ float g_bc1[256], g_bc2[128], g_bc3[64];

__device__ float g_pool[GMAX * 32];
__device__ float g_gcnt[GMAX];

// ---------------- fp8 helpers ----------------
__device__ __forceinline__ uint16_t pack_e4m3(float v0, float v1) {
    // v0 -> low byte, v1 -> high byte (first PTX operand goes to upper half)
    uint16_t r;
    asm("cvt.rn.satfinite.e4m3x2.f32 %0, %1, %2;" : "=h"(r) : "f"(v1), "f"(v0));
    return r;
}
__device__ __forceinline__ __half2 e4_h2(uint16_t u) {
    uint32_t h;
    asm("cvt.rn.f16x2.e4m3x2 %0, %1;" : "=r"(h) : "h"(u));
    return *(__half2*)&h;
}

// ---------------- init: zero counters + convert x to bf16 ----------------
__global__ void init_kernel(const float* __restrict__ x, int n, int g) {
    int i = blockIdx.x * blockDim.x + threadIdx.x;
    if (i == 0)      g_total   = 0;
    if (i < n)       g_deg[i]  = 0;
    if (i < g * 32)  g_pool[i] = 0.f;
    if (i < g)       g_gcnt[i] = 0.f;
    if (i < n * 32)  g_Xb[i]   = __float2bfloat16(x[i]);
}

__global__ void hist_kernel(const int* __restrict__ dst, int e) {
    int i = blockIdx.x * blockDim.x + threadIdx.x;
    if (i < e) atomicAdd(&g_deg[dst[i]], 1);
}

__global__ void alloc_kernel(int n, const int* __restrict__ batch) {
    int i = blockIdx.x * blockDim.x + threadIdx.x;
    int lane = threadIdx.x & 31;
    int d = (i < n) ? g_deg[i] : 0;
    int pre = d;
    #pragma unroll
    for (int s = 1; s < 32; s <<= 1) {
        int t = __shfl_up_sync(0xffffffffu, pre, s);
        if (lane >= s) pre += t;
    }
    int wsum = __shfl_sync(0xffffffffu, pre, 31);
    int base = 0;
    if (lane == 31) base = atomicAdd(&g_total, wsum);
    base = __shfl_sync(0xffffffffu, base, 31);
    int off = base + pre - d;
    if (i < n) {
        g_off[i] = off; g_pos[i] = off;
        atomicAdd(&g_gcnt[batch[i]], 1.f);
    }
}

__global__ void scatter_kernel(const int* __restrict__ src,
                               const int* __restrict__ dst, int e) {
    int i = blockIdx.x * blockDim.x + threadIdx.x;
    if (i < e) {
        int p = atomicAdd(&g_pos[dst[i]], 1);
        g_srt_src[p] = src[i];
    }
}

// ---------------- single-launch weight prep ----------------
__global__ void prep_weights(const float* Wn,  const float* W1a, const float* b1a,
                             const float* W1b, const float* W2a, const float* b2a,
                             const float* W2b, const float* W3a, const float* b3a,
                             const float* W3b) {
    const int S0 = 64 * 32;
    const int S1 = 256 * 64;
    const int S2 = 128 * 128;
    const int S3 = 128 * 128;
    const int S4 = 64 * 64;
    const int S5 = 64 * 64;
    const int S6 = 32 * 32;
    const int TOT = S0 + S1 + S2 + S3 + S4 + S5 + S6;
    for (int i = blockIdx.x * blockDim.x + threadIdx.x; i < TOT;
         i += gridDim.x * blockDim.x) {
        int j = i;
        if (j < S0) { int c = j / 32, k = j % 32;
            g_Wtn[j] = __float2bfloat16(Wn[k * 64 + c]); continue; } j -= S0;
        if (j < S1) { int c = j / 64, k = j % 64;
            float v = (c < 128) ? W1a[k * 128 + c] - W1a[(k + 64) * 128 + c]
                                : W1a[(k + 64) * 128 + (c - 128)];
            g_Wct1[j] = __float2bfloat16(v);
            if (k == 0) g_bc1[c] = (c < 128) ? b1a[c] : 0.f;
            continue; } j -= S1;
        if (j < S2) { int c = j / 128, k = j % 128;
            g_Wt1b[j] = __float2bfloat16(W1b[k * 128 + c]); continue; } j -= S2;
        if (j < S3) { int c = j / 128, k = j % 128;
            float v = (c < 64) ? W2a[k * 64 + c] - W2a[(k + 128) * 64 + c]
                               : W2a[(k + 128) * 64 + (c - 64)];
            g_Wct2[j] = __float2bfloat16(v);
            if (k == 0) g_bc2[c] = (c < 64) ? b2a[c] : 0.f;
            continue; } j -= S3;
        if (j < S4) { int c = j / 64, k = j % 64;
            g_Wt2b[j] = __float2bfloat16(W2b[k * 64 + c]); continue; } j -= S4;
        if (j < S5) { int c = j / 64, k = j % 64;
            float v = (c < 32) ? W3a[k * 32 + c] - W3a[(k + 64) * 32 + c]
                               : W3a[(k + 64) * 32 + (c - 32)];
            g_Wct3[j] = __float2bfloat16(v);
            if (k == 0) g_bc3[c] = (c < 32) ? b3a[c] : 0.f;
            continue; } j -= S5;
        { int c = j / 32, k = j % 32;
            g_Wt3b[j] = __float2bfloat16(W3b[k * 32 + c]); }
    }
}

// ---------------- bf16 mma ----------------
__device__ __forceinline__ void mma_bf16(float* c, const uint32_t* a, const uint32_t* b) {
    asm volatile(
        "mma.sync.aligned.m16n8k16.row.col.f32.bf16.bf16.f32 "
        "{%0,%1,%2,%3}, {%4,%5,%6,%7}, {%8,%9}, {%0,%1,%2,%3};"
        : "+f"(c[0]), "+f"(c[1]), "+f"(c[2]), "+f"(c[3])
        : "r"(a[0]), "r"(a[1]), "r"(a[2]), "r"(a[3]), "r"(b[0]), "r"(b[1]));
}

// ======== fused 2-stage GEMM: X[N,K1] -> T=epi1(X@W1) [64,H1] in smem ->
//          AB = T@W2 + b2, emitted as fp8 [N,WOUT] ========
// EPI1=0: T = acc + b1[c]
// EPI1=1: T = relu((acc + b1[c]*[deg>0]) * gam[c]/sqrt(1+eps) + bet[c])
template <int K1, int H1, int WOUT, int EPI1>
__global__ __launch_bounds__(256)
void fused_gemm(const bf16* __restrict__ X, const bf16* __restrict__ W1t,
                const float* __restrict__ b1, const float* __restrict__ gam,
                const float* __restrict__ bet, const bf16* __restrict__ W2t,
                const float* __restrict__ b2, uint8_t* __restrict__ AB, int nrows) {
    constexpr int BM  = 64;
    constexpr int RS  = 20;              // uint32 row stride (16 data + 4 pad)
    constexpr int NJ1 = H1 / 16;
    constexpr int NJ2 = WOUT / 16;
    constexpr int ST  = H1 + 8;          // sT bf16 row stride
    constexpr int BMAX = (H1 > WOUT) ? H1 : WOUT;

    __shared__ uint32_t sA[BM * RS];
    __shared__ uint32_t sB[BMAX * RS];   // reused: stage-1 W1 tile, then stage-2 W2 tile
    __shared__ bf16     sT[BM * ST];

    const int tid  = threadIdx.x;
    const int lane = tid & 31;
    const int wid  = tid >> 5;
    const int wm   = wid & 3;            // 4 warps along m (16 rows each)
    const int wn   = wid >> 2;           // 2 warps along n
    const int gq   = lane >> 2;
    const int t4   = lane & 3;
    const int row0 = blockIdx.x * BM;

    // ---------------- stage 1 ----------------
    float acc1[NJ1][4];
    #pragma unroll
    for (int nj = 0; nj < NJ1; nj++)
        #pragma unroll
        for (int q = 0; q < 4; q++) acc1[nj][q] = 0.f;

    for (int kt = 0; kt < K1; kt += 32) {
        {   // A tile: 64 rows x 32 bf16
            int row = tid >> 2, q = tid & 3;
            int gr  = row0 + row;
            uint4 v = make_uint4(0u, 0u, 0u, 0u);
            if (gr < nrows) v = *(const uint4*)&X[(size_t)gr * K1 + kt + q * 8];
            *(uint4*)&sA[row * RS + q * 4] = v;
        }
        #pragma unroll
        for (int t = 0; t < (H1 * 4 + 255) / 256; t++) {
            int i = tid + t * 256;
            if (i < H1 * 4) {
                int row = i >> 2, q = i & 3;
                *(uint4*)&sB[row * RS + q * 4] =
                    *(const uint4*)&W1t[(size_t)row * K1 + kt + q * 8];
            }
        }
        __syncthreads();
        #pragma unroll
        for (int ks = 0; ks < 2; ks++) {
            uint32_t a[4];
            int r = wm * 16 + gq;
            a[0] = sA[r * RS + ks * 8 + t4];
            a[1] = sA[(r + 8) * RS + ks * 8 + t4];
            a[2] = sA[r * RS + ks * 8 + t4 + 4];
            a[3] = sA[(r + 8) * RS + ks * 8 + t4 + 4];
            #pragma unroll
            for (int nj = 0; nj < NJ1; nj++) {
                int nr = wn * (H1 / 2) + nj * 8 + gq;
                uint32_t b[2] = { sB[nr * RS + ks * 8 + t4],
                                  sB[nr * RS + ks * 8 + t4 + 4] };
                mma_bf16(acc1[nj], a, b);
            }
        }
        __syncthreads();
    }

    // stage-1 epilogue -> sT (bf16)
    const float rsc = rsqrtf(1.f + 1e-5f);
    #pragma unroll
    for (int hf = 0; hf < 2; hf++) {
        int row = wm * 16 + gq + hf * 8;
        int gr  = row0 + row;
        float ind = 1.f;
        if (EPI1 == 1) ind = (g_deg[gr] > 0) ? 1.f : 0.f;   // gr < NMAX always
        #pragma unroll
        for (int nj = 0; nj < NJ1; nj++) {
            int c = wn * (H1 / 2) + nj * 8 + 2 * t4;
            float v0 = acc1[nj][hf * 2 + 0];
            float v1 = acc1[nj][hf * 2 + 1];
            if (EPI1 == 0) {
                v0 += b1[c]; v1 += b1[c + 1];
            } else {
                v0 = fmaxf(fmaf(v0 + b1[c]     * ind, gam[c]     * rsc, bet[c]),     0.f);
                v1 = fmaxf(fmaf(v1 + b1[c + 1] * ind, gam[c + 1] * rsc, bet[c + 1]), 0.f);
            }
            *(bf162*)&sT[row * ST + c] = __floats2bfloat162_rn(v0, v1);
        }
    }

    // ---------------- stage 2 ----------------
    float acc2[NJ2][4];
    #pragma unroll
    for (int nj = 0; nj < NJ2; nj++)
        #pragma unroll
        for (int q = 0; q < 4; q++) acc2[nj][q] = 0.f;

    for (int kt = 0; kt < H1; kt += 32) {
        __syncthreads();
        #pragma unroll
        for (int t = 0; t < (WOUT * 4 + 255) / 256; t++) {
            int i = tid + t * 256;
            if (i < WOUT * 4) {
                int row = i >> 2, q = i & 3;
                *(uint4*)&sB[row * RS + q * 4] =
                    *(const uint4*)&W2t[(size_t)row * H1 + kt + q * 8];
            }
        }
        __syncthreads();
        #pragma unroll
        for (int ks = 0; ks < 2; ks++) {
            uint32_t a[4];
            int r  = wm * 16 + gq;
            int kc = kt + ks * 16 + 2 * t4;
            a[0] = *(const uint32_t*)&sT[r * ST + kc];
            a[1] = *(const uint32_t*)&sT[(r + 8) * ST + kc];
            a[2] = *(const uint32_t*)&sT[r * ST + kc + 8];
            a[3] = *(const uint32_t*)&sT[(r + 8) * ST + kc + 8];
            #pragma unroll
            for (int nj = 0; nj < NJ2; nj++) {
                int nr = wn * (WOUT / 2) + nj * 8 + gq;
                uint32_t b[2] = { sB[nr * RS + ks * 8 + t4],
                                  sB[nr * RS + ks * 8 + t4 + 4] };
                mma_bf16(acc2[nj], a, b);
            }
        }
    }

    // stage-2 epilogue: +bias, convert to e4m3, store
    #pragma unroll
    for (int hf = 0; hf < 2; hf++) {
        int gr = row0 + wm * 16 + gq + hf * 8;
        if (gr >= nrows) continue;
        #pragma unroll
        for (int nj = 0; nj < NJ2; nj++) {
            int c = wn * (WOUT / 2) + nj * 8 + 2 * t4;
            float v0 = acc2[nj][hf * 2 + 0] + b2[c];
            float v1 = acc2[nj][hf * 2 + 1] + b2[c + 1];
            *(uint16_t*)&AB[(size_t)gr * WOUT + c] = pack_e4m3(v0, v1);
        }
    }
}

// ======== last GEMM: pool += bnrelu(M3 @ W3b) (H=32) ========
__global__ __launch_bounds__(256)
void last_gemm(const bf16* __restrict__ X, const bf16* __restrict__ Wt,
               const float* __restrict__ bias, const float* __restrict__ gam,
               const float* __restrict__ bet, const int* __restrict__ batch,
               int nrows) {
    constexpr int K = 32, H = 32, BM = 256, RS = 20;
    __shared__ uint32_t sA[BM * RS];
    __shared__ uint32_t sB[H * RS];

    const int tid  = threadIdx.x;
    const int lane = tid & 31;
    const int wid  = tid >> 5;          // 8 warps along m
    const int row0 = blockIdx.x * BM;
    const int gq   = lane >> 2;
    const int t4   = lane & 3;

    float acc[2][4][4];
    #pragma unroll
    for (int mi = 0; mi < 2; mi++)
        #pragma unroll
        for (int nj = 0; nj < 4; nj++)
            #pragma unroll
            for (int q = 0; q < 4; q++) acc[mi][nj][q] = 0.f;

    #pragma unroll
    for (int t = 0; t < 4; t++) {
        int i = tid + t * 256;
        int row = i >> 2, q = i & 3;
        int gr = row0 + row;
        uint4 v = make_uint4(0u, 0u, 0u, 0u);
        if (gr < nrows) v = *(const uint4*)&X[(size_t)gr * K + q * 8];
        *(uint4*)&sA[row * RS + q * 4] = v;
    }
    if (tid < H * 4) {
        int row = tid >> 2, q = tid & 3;
        *(uint4*)&sB[row * RS + q * 4] = *(const uint4*)&Wt[(size_t)row * K + q * 8];
    }
    __syncthreads();

    #pragma unroll
    for (int ks = 0; ks < 2; ks++) {
        uint32_t a[2][4], b[4][2];
        #pragma unroll
        for (int mi = 0; mi < 2; mi++) {
            int r = wid * 32 + mi * 16 + gq;
            a[mi][0] = sA[r * RS + ks * 8 + t4];
            a[mi][1] = sA[(r + 8) * RS + ks * 8 + t4];
            a[mi][2] = sA[r * RS + ks * 8 + t4 + 4];
            a[mi][3] = sA[(r + 8) * RS + ks * 8 + t4 + 4];
        }
        #pragma unroll
        for (int nj = 0; nj < 4; nj++) {
            int nr = nj * 8 + gq;
            b[nj][0] = sB[nr * RS + ks * 8 + t4];
            b[nj][1] = sB[nr * RS + ks * 8 + t4 + 4];
        }
        #pragma unroll
        for (int mi = 0; mi < 2; mi++)
            #pragma unroll
            for (int nj = 0; nj < 4; nj++)
                mma_bf16(acc[mi][nj], a[mi], b[nj]);
    }

    const float rsc = rsqrtf(1.f + 1e-5f);
    #pragma unroll
    for (int mi = 0; mi < 2; mi++) {
        #pragma unroll
        for (int hf = 0; hf < 2; hf++) {
            int gr = row0 + wid * 32 + mi * 16 + gq + hf * 8;
            if (gr >= nrows) continue;
            float ind = (g_deg[gr] > 0) ? 1.f : 0.f;
            int pb = batch[gr] * 32;
            #pragma unroll
            for (int nj = 0; nj < 4; nj++) {
                int c = nj * 8 + 2 * t4;
                float v0 = acc[mi][nj][hf * 2 + 0];
                float v1 = acc[mi][nj][hf * 2 + 1];
                v0 = fmaxf(fmaf(v0 + bias[c]     * ind, gam[c]     * rsc, bet[c]),     0.f);
                v1 = fmaxf(fmaf(v1 + bias[c + 1] * ind, gam[c + 1] * rsc, bet[c + 1]), 0.f);
                atomicAdd(&g_pool[pb + c],     v0);
                atomicAdd(&g_pool[pb + c + 1], v1);
            }
        }
    }
}

// ------- edge aggregation: M[v] = mean_e relu(A[v]+B[src_e]); AB fp8 -------
template <int H>
__global__ void edge_agg_kernel(int n) {
    constexpr int LPN = H / 4;           // lanes per node (4 fp8 per lane)
    constexpr int NPW = 32 / LPN;
    int gw   = (blockIdx.x * blockDim.x + threadIdx.x) >> 5;
    int lane = threadIdx.x & 31;
    int sub  = lane / LPN;
    int sl   = lane % LPN;
    int w    = gw * NPW + sub;
    if (w >= n) return;

    const uint8_t* ABp = g_AB;
    uint32_t a32 = *(const uint32_t*)(ABp + (size_t)w * 2 * H + sl * 4);
    __half2 aL = e4_h2((uint16_t)a32);
    __half2 aH = e4_h2((uint16_t)(a32 >> 16));
    __half2 z    = __float2half2_rn(0.f);
    __half2 accL = z, accH = z;

    int st = g_off[w];
    int d  = g_deg[w];
    int en = st + d;
    int e  = st;

    for (; e + 4 <= en; e += 4) {
        int s0 = g_srt_src[e];
        int s1 = g_srt_src[e + 1];
        int s2 = g_srt_src[e + 2];
        int s3 = g_srt_src[e + 3];
        uint32_t b0 = *(const uint32_t*)(ABp + (size_t)s0 * 2 * H + H + sl * 4);
        uint32_t b1 = *(const uint32_t*)(ABp + (size_t)s1 * 2 * H + H + sl * 4);
        uint32_t b2 = *(const uint32_t*)(ABp + (size_t)s2 * 2 * H + H + sl * 4);
        uint32_t b3 = *(const uint32_t*)(ABp + (size_t)s3 * 2 * H + H + sl * 4);
        #pragma unroll
        for (int q = 0; q < 4; q++) {
            uint32_t bq = (q == 0) ? b0 : (q == 1) ? b1 : (q == 2) ? b2 : b3;
            accL = __hadd2(accL, __hmax2(__hadd2(aL, e4_h2((uint16_t)bq)), z));
            accH = __hadd2(accH, __hmax2(__hadd2(aH, e4_h2((uint16_t)(bq >> 16))), z));
        }
    }
    for (; e < en; e++) {
        int s = g_srt_src[e];
        uint32_t bq = *(const uint32_t*)(ABp + (size_t)s * 2 * H + H + sl * 4);
        accL = __hadd2(accL, __hmax2(__hadd2(aL, e4_h2((uint16_t)bq)), z));
        accH = __hadd2(accH, __hmax2(__hadd2(aH, e4_h2((uint16_t)(bq >> 16))), z));
    }

    float2 fL = __half22float2(accL);
    float2 fH = __half22float2(accH);
    float inv = 1.f / (float)max(d, 1);
    bf162 o01 = __floats2bfloat162_rn(fL.x * inv, fL.y * inv);
    bf162 o23 = __floats2bfloat162_rn(fH.x * inv, fH.y * inv);
    uint2 ov;
    ov.x = *(uint32_t*)&o01;
    ov.y = *(uint32_t*)&o23;
    *(uint2*)&g_M[(size_t)w * H + sl * 4] = ov;
}

// ---------------- classifier ----------------
__global__ void final_kernel(const float* __restrict__ Wfc,
                             const float* __restrict__ bfc,
                             float* __restrict__ out, int g) {
    int t = blockIdx.x * blockDim.x + threadIdx.x;
    if (t >= g * 5) return;
    int gi = t / 5, o = t % 5;
    float inv = 1.f / fmaxf(g_gcnt[gi], 1.f);
    float z = bfc[o];
    #pragma unroll
    for (int k = 0; k < 32; k++)
        z = fmaf(g_pool[gi * 32 + k] * inv, Wfc[k * 5 + o], z);
    out[t] = 1.f / (1.f + expf(-z));
}

// ---------------- launch ----------------
static inline int cdiv(int a, int b) { return (a + b - 1) / b; }

extern "C" void kernel_launch(void* const* d_in, const int* in_sizes, int n_in,
                              void* d_out, int out_size) {
    const float* x     = (const float*)d_in[0];
    const float* Wn    = (const float*)d_in[4];
    const float* bnode = (const float*)d_in[5];
    const float* W1a   = (const float*)d_in[6];
    const float* b1a   = (const float*)d_in[7];
    const float* W1b   = (const float*)d_in[8];
    const float* b1b   = (const float*)d_in[9];
    const float* W2a   = (const float*)d_in[10];
    const float* b2a   = (const float*)d_in[11];
    const float* W2b   = (const float*)d_in[12];
    const float* b2b   = (const float*)d_in[13];
    const float* W3a   = (const float*)d_in[14];
    const float* b3a   = (const float*)d_in[15];
    const float* W3b   = (const float*)d_in[16];
    const float* b3b   = (const float*)d_in[17];
    const float* gm1   = (const float*)d_in[18];
    const float* bt1   = (const float*)d_in[19];
    const float* gm2   = (const float*)d_in[20];
    const float* bt2   = (const float*)d_in[21];
    const float* gm3   = (const float*)d_in[22];
    const float* bt3   = (const float*)d_in[23];
    const float* Wfc   = (const float*)d_in[24];
    const float* bfc   = (const float*)d_in[25];
    const int*   ei    = (const int*)d_in[26];
    const int*   batch = (const int*)d_in[27];

    const int n = in_sizes[0] / 32;
    const int e = in_sizes[26] / 2;
    const int g = out_size / 5;

    const int* src = ei;
    const int* dst = ei + e;

    bf16 *Xb, *M, *Wtn, *Wct1, *Wt1b, *Wct2, *Wt2b, *Wct3, *Wt3b;
    uint8_t* AB;
    float *bc1, *bc2, *bc3;
    cudaGetSymbolAddress((void**)&Xb,   g_Xb);
    cudaGetSymbolAddress((void**)&M,    g_M);
    cudaGetSymbolAddress((void**)&AB,   g_AB);
    cudaGetSymbolAddress((void**)&Wtn,  g_Wtn);
    cudaGetSymbolAddress((void**)&Wct1, g_Wct1);
    cudaGetSymbolAddress((void**)&Wt1b, g_Wt1b);
    cudaGetSymbolAddress((void**)&Wct2, g_Wct2);
    cudaGetSymbolAddress((void**)&Wt2b, g_Wt2b);
    cudaGetSymbolAddress((void**)&Wct3, g_Wct3);
    cudaGetSymbolAddress((void**)&Wt3b, g_Wt3b);
    cudaGetSymbolAddress((void**)&bc1,  g_bc1);
    cudaGetSymbolAddress((void**)&bc2,  g_bc2);
    cudaGetSymbolAddress((void**)&bc3,  g_bc3);

    init_kernel<<<cdiv(n * 32, 256), 256>>>(x, n, g);
    hist_kernel<<<cdiv(e, 256), 256>>>(dst, e);
    alloc_kernel<<<cdiv(n, 256), 256>>>(n, batch);
    scatter_kernel<<<cdiv(e, 256), 256>>>(src, dst, e);
    prep_weights<<<236, 256>>>(Wn, W1a, b1a, W1b, W2a, b2a, W2b, W3a, b3a, W3b);

    // ---- layer 1 (fused: x -> h0 -> AB1 fp8[N,256]) ----
    fused_gemm<32, 64, 256, 0><<<cdiv(n, 64), 256>>>(
        Xb, Wtn, bnode, nullptr, nullptr, Wct1, bc1, AB, n);
    edge_agg_kernel<128><<<cdiv(n, 8), 256>>>(n);

    // ---- layer 2 (fused: M1 -> h1 -> AB2 fp8[N,128]) ----
    fused_gemm<128, 128, 128, 1><<<cdiv(n, 64), 256>>>(
        M, Wt1b, b1b, gm1, bt1, Wct2, bc2, AB, n);
    edge_agg_kernel<64><<<cdiv(n, 16), 256>>>(n);

    // ---- layer 3 (fused: M2 -> h2 -> AB3 fp8[N,64]) ----
    fused_gemm<64, 64, 64, 1><<<cdiv(n, 64), 256>>>(
        M, Wt2b, b2b, gm2, bt2, Wct3, bc3, AB, n);
    edge_agg_kernel<32><<<cdiv(n, 32), 256>>>(n);

    // ---- pool GEMM + classifier ----
    last_gemm<<<cdiv(n, 256), 256>>>(M, Wt3b, b3b, gm3, bt3, batch, n);
    final_kernel<<<cdiv(g * 5, 256), 256>>>(Wfc, bfc, (float*)d_out, g);
}